// round 2
// baseline (speedup 1.0000x reference)
#include <cuda_runtime.h>
#include <math.h>

#define B_ROWS 16384
#define H_DIM  512
#define K_DIM  512
#define N_OUT  1536   // 3*H

// Scratch for the two GEMM outputs (allocation-free: device globals).
__device__ float g_xt[(size_t)B_ROWS * N_OUT];
__device__ float g_ht[(size_t)B_ROWS * N_OUT];

#define BM 128
#define BN 128
#define BK 16

// C[m, n] = sum_k A[m,k] * W[n,k] + bias[n]
// A: [M, 512] row-major, W: [1536, 512] row-major. Shapes hardcoded (all divisible).
__global__ __launch_bounds__(256) void gemm_bias_kernel(
    const float* __restrict__ A, const float* __restrict__ W,
    const float* __restrict__ bias, int which)
{
    float* __restrict__ C = which ? g_ht : g_xt;

    __shared__ float As[BK][BM];
    __shared__ float Bs[BK][BN];

    const int tid = threadIdx.x;
    const int m0 = blockIdx.y * BM;
    const int n0 = blockIdx.x * BN;

    const int ty = tid >> 4;   // 0..15 -> row group
    const int tx = tid & 15;   // 0..15 -> col group

    float acc[8][8];
#pragma unroll
    for (int i = 0; i < 8; i++)
#pragma unroll
        for (int j = 0; j < 8; j++) acc[i][j] = 0.f;

    for (int k0 = 0; k0 < K_DIM; k0 += BK) {
        // Load A tile (128x16) and W tile (128x16), transposed into smem [k][mn].
        // 512 float4 per tile, 256 threads -> 2 each.
#pragma unroll
        for (int l = 0; l < 2; l++) {
            int f   = tid + l * 256;     // 0..511
            int row = f >> 2;            // 0..127
            int c4  = (f & 3) * 4;       // 0,4,8,12

            float4 av = *(const float4*)&A[(size_t)(m0 + row) * K_DIM + k0 + c4];
            As[c4 + 0][row] = av.x;
            As[c4 + 1][row] = av.y;
            As[c4 + 2][row] = av.z;
            As[c4 + 3][row] = av.w;

            float4 bv = *(const float4*)&W[(size_t)(n0 + row) * K_DIM + k0 + c4];
            Bs[c4 + 0][row] = bv.x;
            Bs[c4 + 1][row] = bv.y;
            Bs[c4 + 2][row] = bv.z;
            Bs[c4 + 3][row] = bv.w;
        }
        __syncthreads();

#pragma unroll
        for (int k = 0; k < BK; k++) {
            float a[8], b[8];
            float4 a0 = *(const float4*)&As[k][ty * 8];
            float4 a1 = *(const float4*)&As[k][ty * 8 + 4];
            float4 b0 = *(const float4*)&Bs[k][tx * 8];
            float4 b1 = *(const float4*)&Bs[k][tx * 8 + 4];
            a[0] = a0.x; a[1] = a0.y; a[2] = a0.z; a[3] = a0.w;
            a[4] = a1.x; a[5] = a1.y; a[6] = a1.z; a[7] = a1.w;
            b[0] = b0.x; b[1] = b0.y; b[2] = b0.z; b[3] = b0.w;
            b[4] = b1.x; b[5] = b1.y; b[6] = b1.z; b[7] = b1.w;
#pragma unroll
            for (int i = 0; i < 8; i++)
#pragma unroll
                for (int j = 0; j < 8; j++)
                    acc[i][j] += a[i] * b[j];
        }
        __syncthreads();
    }

    // Write out with bias (vectorized).
#pragma unroll
    for (int i = 0; i < 8; i++) {
        const int m = m0 + ty * 8 + i;
#pragma unroll
        for (int j = 0; j < 8; j += 4) {
            const int n = n0 + tx * 8 + j;
            float4 o;
            o.x = acc[i][j + 0] + bias[n + 0];
            o.y = acc[i][j + 1] + bias[n + 1];
            o.z = acc[i][j + 2] + bias[n + 2];
            o.w = acc[i][j + 3] + bias[n + 3];
            *(float4*)&C[(size_t)m * N_OUT + n] = o;
        }
    }
}

// One block per row. 256 threads. Each thread loads exactly the values it needs
// for both the LN reductions and its two output columns (t, t+256).
__global__ __launch_bounds__(256) void epilogue_kernel(
    const float* __restrict__ hx, float* __restrict__ out)
{
    const int row = blockIdx.x;
    const int t = threadIdx.x;
    const float* __restrict__ xr = g_xt + (size_t)row * N_OUT;
    const float* __restrict__ hr = g_ht + (size_t)row * N_OUT;

    float xg[4], hg[4], xn[2], hn[2];
#pragma unroll
    for (int i = 0; i < 4; i++) {
        xg[i] = xr[t + i * 256];
        hg[i] = hr[t + i * 256];
    }
#pragma unroll
    for (int i = 0; i < 2; i++) {
        xn[i] = xr[1024 + t + i * 256];
        hn[i] = hr[1024 + t + i * 256];
    }

    // 8 statistics: sum & sumsq for (xt gates 0:1024), (ht gates 0:1024),
    // (xt cand 1024:1536), (ht cand 1024:1536)
    float v[8];
    v[0] = xg[0] + xg[1] + xg[2] + xg[3];
    v[1] = xg[0]*xg[0] + xg[1]*xg[1] + xg[2]*xg[2] + xg[3]*xg[3];
    v[2] = hg[0] + hg[1] + hg[2] + hg[3];
    v[3] = hg[0]*hg[0] + hg[1]*hg[1] + hg[2]*hg[2] + hg[3]*hg[3];
    v[4] = xn[0] + xn[1];
    v[5] = xn[0]*xn[0] + xn[1]*xn[1];
    v[6] = hn[0] + hn[1];
    v[7] = hn[0]*hn[0] + hn[1]*hn[1];

    __shared__ float red[8][8];
    __shared__ float fin[8];
    const int lane = t & 31;
    const int warp = t >> 5;

#pragma unroll
    for (int s = 0; s < 8; s++) {
#pragma unroll
        for (int off = 16; off > 0; off >>= 1)
            v[s] += __shfl_down_sync(0xffffffffu, v[s], off);
    }
    if (lane == 0) {
#pragma unroll
        for (int s = 0; s < 8; s++) red[warp][s] = v[s];
    }
    __syncthreads();
    if (t < 8) {
        float s = 0.f;
#pragma unroll
        for (int w = 0; w < 8; w++) s += red[w][t];
        fin[t] = s;
    }
    __syncthreads();

    const float inv1024 = 1.f / 1024.f;
    const float inv512  = 1.f / 512.f;
    const float m_xg = fin[0] * inv1024;
    const float r_xg = rsqrtf(fin[1] * inv1024 - m_xg * m_xg + 1e-5f);
    const float m_hg = fin[2] * inv1024;
    const float r_hg = rsqrtf(fin[3] * inv1024 - m_hg * m_hg + 1e-5f);
    const float m_xn = fin[4] * inv512;
    const float r_xn = rsqrtf(fin[5] * inv512 - m_xn * m_xn + 1e-5f);
    const float m_hn = fin[6] * inv512;
    const float r_hn = rsqrtf(fin[7] * inv512 - m_hn * m_hn + 1e-5f);

#pragma unroll
    for (int i = 0; i < 2; i++) {
        const int col = t + i * 256;
        // r gate: columns [0,512), z gate: columns [512,1024) of LN'd gate slice
        float pre_r = (xg[i] - m_xg) * r_xg + (hg[i] - m_hg) * r_hg;
        float pre_z = (xg[i + 2] - m_xg) * r_xg + (hg[i + 2] - m_hg) * r_hg;
        float rg = 1.f / (1.f + __expf(-pre_r));
        float zg = 1.f / (1.f + __expf(-pre_z));
        float nt = tanhf((xn[i] - m_xn) * r_xn + rg * ((hn[i] - m_hn) * r_hn));
        float hv = hx[(size_t)row * H_DIM + col];
        out[(size_t)row * H_DIM + col] = zg * hv + (1.f - zg) * nt;
    }
}

extern "C" void kernel_launch(void* const* d_in, const int* in_sizes, int n_in,
                              void* d_out, int out_size)
{
    const float* x     = (const float*)d_in[0];
    const float* hx    = (const float*)d_in[1];
    const float* W_i2h = (const float*)d_in[2];
    const float* b_i2h = (const float*)d_in[3];
    const float* W_h2h = (const float*)d_in[4];
    const float* b_h2h = (const float*)d_in[5];
    float* out = (float*)d_out;

    dim3 grid(N_OUT / BN, B_ROWS / BM);  // (12, 128)
    gemm_bias_kernel<<<grid, 256>>>(x,  W_i2h, b_i2h, 0);
    gemm_bias_kernel<<<grid, 256>>>(hx, W_h2h, b_h2h, 1);
    epilogue_kernel<<<B_ROWS, 256>>>(hx, out);
}

// round 4
// speedup vs baseline: 3.3655x; 3.3655x over previous
#include <cuda_runtime.h>
#include <math.h>
#include <cstdint>

#define B_ROWS 16384
#define H_DIM  512
#define K_DIM  512
#define N_OUT  1536   // 3*H

// Scratch for the two GEMM outputs (allocation-free: device globals).
__device__ float g_xt[(size_t)B_ROWS * N_OUT];
__device__ float g_ht[(size_t)B_ROWS * N_OUT];

// ─────────────── tiling ───────────────
#define BM 128
#define BN 128
#define BK 32
#define PITCH (BK + 4)                 // 36 floats: (36*m + k) % 32 = (4m+k)%32 -> conflict-free
#define ASZ (BM * PITCH)               // floats per tile buffer
#define SMEM_FLOATS (4 * ASZ)          // A0,A1,B0,B1
#define SMEM_BYTES  (SMEM_FLOATS * 4)  // 73728
#define KSTAGES (K_DIM / BK)           // 16

__device__ __forceinline__ uint32_t smem_to_u32(const void* p) {
    uint32_t a;
    asm("{ .reg .u64 t; cvta.to.shared.u64 t, %1; cvt.u32.u64 %0, t; }"
        : "=r"(a) : "l"(p));
    return a;
}

__device__ __forceinline__ void cp_async16(uint32_t dst, const void* src) {
    asm volatile("cp.async.cg.shared.global [%0], [%1], 16;"
                 :: "r"(dst), "l"(src) : "memory");
}
#define CP_COMMIT() asm volatile("cp.async.commit_group;" ::: "memory")
#define CP_WAIT(n)  asm volatile("cp.async.wait_group %0;" :: "n"(n) : "memory")

__device__ __forceinline__ void mma_tf32(
    float& c0, float& c1, float& c2, float& c3,
    uint32_t a0, uint32_t a1, uint32_t a2, uint32_t a3,
    uint32_t b0, uint32_t b1)
{
    asm volatile(
        "mma.sync.aligned.m16n8k8.row.col.f32.tf32.tf32.f32 "
        "{%0,%1,%2,%3}, {%4,%5,%6,%7}, {%8,%9}, {%0,%1,%2,%3};"
        : "+f"(c0), "+f"(c1), "+f"(c2), "+f"(c3)
        : "r"(a0), "r"(a1), "r"(a2), "r"(a3), "r"(b0), "r"(b1));
}

// Fill one 128x32 fp32 tile (A and B halves) via 16B cp.async, gmem-native [row][k] layout.
__device__ __forceinline__ void load_stage(
    uint32_t a_smem, uint32_t b_smem,
    const float* __restrict__ A, const float* __restrict__ W,
    int m0, int n0, int k0, int tid)
{
    // 128 rows x 8 chunks = 1024 chunks per operand; 256 threads -> 4 each.
#pragma unroll
    for (int i = 0; i < 4; i++) {
        int c   = i * 256 + tid;          // 0..1023
        int row = c >> 3;                 // 0..127
        int ch  = c & 7;                  // 16B chunk (4 floats)
        uint32_t off = (uint32_t)(row * PITCH + ch * 4) * 4u;
        cp_async16(a_smem + off, A + (size_t)(m0 + row) * K_DIM + k0 + ch * 4);
        cp_async16(b_smem + off, W + (size_t)(n0 + row) * K_DIM + k0 + ch * 4);
    }
}

// C[m,n] = sum_k A[m,k]*W[n,k] + bias[n]
__global__ __launch_bounds__(256, 2) void gemm_tc_kernel(
    const float* __restrict__ x,  const float* __restrict__ hx,
    const float* __restrict__ Wi, const float* __restrict__ bi,
    const float* __restrict__ Wh, const float* __restrict__ bh)
{
    extern __shared__ float sm[];
    const int tid = threadIdx.x;
    const int which = blockIdx.z;
    const float* __restrict__ A    = which ? hx : x;
    const float* __restrict__ W    = which ? Wh : Wi;
    const float* __restrict__ bias = which ? bh : bi;
    float* __restrict__ C          = which ? g_ht : g_xt;
    const int m0 = blockIdx.y * BM;
    const int n0 = blockIdx.x * BN;

    const uint32_t sm32 = smem_to_u32(sm);
    // buffers: A0 | A1 | B0 | B1
    const uint32_t aoff[2] = { sm32,             sm32 + ASZ * 4u };
    const uint32_t boff[2] = { sm32 + 2u*ASZ*4u, sm32 + 3u*ASZ*4u };

    const int wid  = tid >> 5;
    const int lane = tid & 31;
    const int wr   = wid >> 2;           // 0..1  -> 64-row band
    const int wc   = wid & 3;            // 0..3  -> 32-col band
    const int g    = lane >> 2;          // 0..7
    const int t    = lane & 3;           // 0..3

    float c[4][4][4];
#pragma unroll
    for (int mt = 0; mt < 4; mt++)
#pragma unroll
        for (int nt = 0; nt < 4; nt++)
#pragma unroll
            for (int r = 0; r < 4; r++) c[mt][nt][r] = 0.f;

    // Prologue
    load_stage(aoff[0], boff[0], A, W, m0, n0, 0, tid);
    CP_COMMIT();

    for (int ks = 0; ks < KSTAGES; ks++) {
        const int buf = ks & 1;
        if (ks + 1 < KSTAGES) {
            load_stage(aoff[buf ^ 1], boff[buf ^ 1], A, W, m0, n0, (ks + 1) * BK, tid);
            CP_COMMIT();
            CP_WAIT(1);
        } else {
            CP_WAIT(0);
        }
        __syncthreads();

        const float* Ab = sm + (size_t)(buf) * ASZ + (wr * 64 + g) * PITCH;
        const float* Bb = sm + (size_t)(2 + buf) * ASZ + (wc * 32 + g) * PITCH;

#pragma unroll
        for (int k8 = 0; k8 < 4; k8++) {
            const int kk = k8 * 8 + t;
            uint32_t a[4][4], b[4][2];
#pragma unroll
            for (int mt = 0; mt < 4; mt++) {
                const float* p = Ab + mt * 16 * PITCH;
                a[mt][0] = __float_as_uint(p[kk]);
                a[mt][1] = __float_as_uint(p[8 * PITCH + kk]);
                a[mt][2] = __float_as_uint(p[kk + 4]);
                a[mt][3] = __float_as_uint(p[8 * PITCH + kk + 4]);
            }
#pragma unroll
            for (int nt = 0; nt < 4; nt++) {
                const float* p = Bb + nt * 8 * PITCH;
                b[nt][0] = __float_as_uint(p[kk]);
                b[nt][1] = __float_as_uint(p[kk + 4]);
            }
#pragma unroll
            for (int mt = 0; mt < 4; mt++)
#pragma unroll
                for (int nt = 0; nt < 4; nt++)
                    mma_tf32(c[mt][nt][0], c[mt][nt][1], c[mt][nt][2], c[mt][nt][3],
                             a[mt][0], a[mt][1], a[mt][2], a[mt][3],
                             b[nt][0], b[nt][1]);
        }
        __syncthreads();
    }

    // Store with bias. c0,c1 -> (row, col..col+1); c2,c3 -> (row+8, ...).
#pragma unroll
    for (int mt = 0; mt < 4; mt++) {
        const int row = m0 + wr * 64 + mt * 16 + g;
#pragma unroll
        for (int nt = 0; nt < 4; nt++) {
            const int col = n0 + wc * 32 + nt * 8 + 2 * t;
            const float b0 = bias[col], b1 = bias[col + 1];
            float2 o0 = make_float2(c[mt][nt][0] + b0, c[mt][nt][1] + b1);
            float2 o1 = make_float2(c[mt][nt][2] + b0, c[mt][nt][3] + b1);
            *(float2*)&C[(size_t)row * N_OUT + col] = o0;
            *(float2*)&C[(size_t)(row + 8) * N_OUT + col] = o1;
        }
    }
}

// ─────────────── LN/GRU epilogue (unchanged, verified) ───────────────

__global__ __launch_bounds__(256) void epilogue_kernel(
    const float* __restrict__ hx, float* __restrict__ out)
{
    const int row = blockIdx.x;
    const int t = threadIdx.x;
    const float* __restrict__ xr = g_xt + (size_t)row * N_OUT;
    const float* __restrict__ hr = g_ht + (size_t)row * N_OUT;

    float xg[4], hg[4], xn[2], hn[2];
#pragma unroll
    for (int i = 0; i < 4; i++) {
        xg[i] = xr[t + i * 256];
        hg[i] = hr[t + i * 256];
    }
#pragma unroll
    for (int i = 0; i < 2; i++) {
        xn[i] = xr[1024 + t + i * 256];
        hn[i] = hr[1024 + t + i * 256];
    }

    float v[8];
    v[0] = xg[0] + xg[1] + xg[2] + xg[3];
    v[1] = xg[0]*xg[0] + xg[1]*xg[1] + xg[2]*xg[2] + xg[3]*xg[3];
    v[2] = hg[0] + hg[1] + hg[2] + hg[3];
    v[3] = hg[0]*hg[0] + hg[1]*hg[1] + hg[2]*hg[2] + hg[3]*hg[3];
    v[4] = xn[0] + xn[1];
    v[5] = xn[0]*xn[0] + xn[1]*xn[1];
    v[6] = hn[0] + hn[1];
    v[7] = hn[0]*hn[0] + hn[1]*hn[1];

    __shared__ float red[8][8];
    __shared__ float fin[8];
    const int lane = t & 31;
    const int warp = t >> 5;

#pragma unroll
    for (int s = 0; s < 8; s++) {
#pragma unroll
        for (int off = 16; off > 0; off >>= 1)
            v[s] += __shfl_down_sync(0xffffffffu, v[s], off);
    }
    if (lane == 0) {
#pragma unroll
        for (int s = 0; s < 8; s++) red[warp][s] = v[s];
    }
    __syncthreads();
    if (t < 8) {
        float s = 0.f;
#pragma unroll
        for (int w = 0; w < 8; w++) s += red[w][t];
        fin[t] = s;
    }
    __syncthreads();

    const float inv1024 = 1.f / 1024.f;
    const float inv512  = 1.f / 512.f;
    const float m_xg = fin[0] * inv1024;
    const float r_xg = rsqrtf(fin[1] * inv1024 - m_xg * m_xg + 1e-5f);
    const float m_hg = fin[2] * inv1024;
    const float r_hg = rsqrtf(fin[3] * inv1024 - m_hg * m_hg + 1e-5f);
    const float m_xn = fin[4] * inv512;
    const float r_xn = rsqrtf(fin[5] * inv512 - m_xn * m_xn + 1e-5f);
    const float m_hn = fin[6] * inv512;
    const float r_hn = rsqrtf(fin[7] * inv512 - m_hn * m_hn + 1e-5f);

#pragma unroll
    for (int i = 0; i < 2; i++) {
        const int col = t + i * 256;
        float pre_r = (xg[i] - m_xg) * r_xg + (hg[i] - m_hg) * r_hg;
        float pre_z = (xg[i + 2] - m_xg) * r_xg + (hg[i + 2] - m_hg) * r_hg;
        float rg = 1.f / (1.f + __expf(-pre_r));
        float zg = 1.f / (1.f + __expf(-pre_z));
        float nt = tanhf((xn[i] - m_xn) * r_xn + rg * ((hn[i] - m_hn) * r_hn));
        float hv = hx[(size_t)row * H_DIM + col];
        out[(size_t)row * H_DIM + col] = zg * hv + (1.f - zg) * nt;
    }
}

extern "C" void kernel_launch(void* const* d_in, const int* in_sizes, int n_in,
                              void* d_out, int out_size)
{
    const float* x     = (const float*)d_in[0];
    const float* hx    = (const float*)d_in[1];
    const float* W_i2h = (const float*)d_in[2];
    const float* b_i2h = (const float*)d_in[3];
    const float* W_h2h = (const float*)d_in[4];
    const float* b_h2h = (const float*)d_in[5];
    float* out = (float*)d_out;

    cudaFuncSetAttribute(gemm_tc_kernel,
                         cudaFuncAttributeMaxDynamicSharedMemorySize, SMEM_BYTES);

    dim3 grid(N_OUT / BN, B_ROWS / BM, 2);   // (12, 128, 2)
    gemm_tc_kernel<<<grid, 256, SMEM_BYTES>>>(x, hx, W_i2h, b_i2h, W_h2h, b_h2h);
    epilogue_kernel<<<B_ROWS, 256>>>(hx, out);
}